// round 1
// baseline (speedup 1.0000x reference)
#include <cuda_runtime.h>
#include <math.h>

#define Bv 2
#define Sv 2048
#define Ev 1024
#define Hv 16
#define Dv 64
#define Mtot (Bv * Sv)          // 4096

// Scratch (allocation-free rule: __device__ globals)
__device__ float g_Q[Bv * Hv * Sv * Dv];   // 16 MB
__device__ float g_K[Bv * Hv * Sv * Dv];   // 16 MB
__device__ float g_V[Bv * Hv * Sv * Dv];   // 16 MB
__device__ float g_O[Mtot * Ev];           // 16 MB

enum { MODE_ROPE = 0, MODE_BHSD = 1, MODE_PLAIN = 2 };

// Accurate-enough sincos that survives --use_fast_math:
// Cody-Waite reduction by 2*pi, then fast sincos on the small residual.
__device__ __forceinline__ void sincos_red(float ang, float* s, float* c) {
    float kf = rintf(ang * 0.15915494309189535f);
    float r = fmaf(kf, -6.2831854820251465f, ang);   // hi = float(2*pi)
    r = fmaf(kf, 1.7484555e-7f, r);                  // -lo correction
    __sincosf(r, s, c);
}

// ---------------------------------------------------------------------------
// NT GEMM: C[m,n] = sum_k A[m,k] * W[n,k] + bias[n]
// A: [M x 1024] row-major, W: [N x 1024] row-major (K contiguous for both).
// Tile 64x64, BK=16, 256 threads, 4x4 micro-tile per thread.
// ---------------------------------------------------------------------------
__global__ __launch_bounds__(256)
void gemm_nt_kernel(const float* __restrict__ A, const float* __restrict__ W,
                    const float* __restrict__ bias, float* __restrict__ dst,
                    int mode)
{
    __shared__ float As[16][64];   // [k][m]
    __shared__ float Ws[16][64];   // [k][n]

    const int K = Ev;
    int tid = threadIdx.x;
    int tx = tid & 15;             // micro col group
    int ty = tid >> 4;             // micro row group
    int m0 = blockIdx.y << 6;
    int n0 = blockIdx.x << 6;

    int lm = tid >> 2;             // 0..63 (tile row to load)
    int lk = (tid & 3) << 2;       // 0,4,8,12

    const float* Arow = A + (size_t)(m0 + lm) * K + lk;
    const float* Wrow = W + (size_t)(n0 + lm) * K + lk;

    float acc[4][4] = {};

    for (int k0 = 0; k0 < K; k0 += 16) {
        float4 a = *(const float4*)(Arow + k0);
        float4 w = *(const float4*)(Wrow + k0);
        As[lk + 0][lm] = a.x; As[lk + 1][lm] = a.y;
        As[lk + 2][lm] = a.z; As[lk + 3][lm] = a.w;
        Ws[lk + 0][lm] = w.x; Ws[lk + 1][lm] = w.y;
        Ws[lk + 2][lm] = w.z; Ws[lk + 3][lm] = w.w;
        __syncthreads();

        #pragma unroll
        for (int k = 0; k < 16; k++) {
            float4 a4 = *(const float4*)&As[k][ty << 2];
            float4 w4 = *(const float4*)&Ws[k][tx << 2];
            float av[4] = {a4.x, a4.y, a4.z, a4.w};
            float wv[4] = {w4.x, w4.y, w4.z, w4.w};
            #pragma unroll
            for (int i = 0; i < 4; i++)
                #pragma unroll
                for (int j = 0; j < 4; j++)
                    acc[i][j] += av[i] * wv[j];
        }
        __syncthreads();
    }

    int nc = n0 + (tx << 2);       // 4 consecutive output cols (aligned to 4)
    float bv4[4];
    #pragma unroll
    for (int j = 0; j < 4; j++) bv4[j] = bias[nc + j];

    if (mode == MODE_PLAIN) {
        #pragma unroll
        for (int i = 0; i < 4; i++) {
            int m = m0 + (ty << 2) + i;
            float4 o;
            o.x = acc[i][0] + bv4[0];
            o.y = acc[i][1] + bv4[1];
            o.z = acc[i][2] + bv4[2];
            o.w = acc[i][3] + bv4[3];
            *(float4*)&dst[(size_t)m * Ev + nc] = o;
        }
    } else if (mode == MODE_BHSD) {
        int h = nc >> 6, d = nc & 63;
        #pragma unroll
        for (int i = 0; i < 4; i++) {
            int m = m0 + (ty << 2) + i;
            int b = m >> 11, s = m & 2047;
            float4 o;
            o.x = acc[i][0] + bv4[0];
            o.y = acc[i][1] + bv4[1];
            o.z = acc[i][2] + bv4[2];
            o.w = acc[i][3] + bv4[3];
            *(float4*)&dst[(((size_t)(b * Hv + h) * Sv + s) << 6) + d] = o;
        }
    } else { // MODE_ROPE: q/k with rotary embedding
        float invf[4];
        #pragma unroll
        for (int j = 0; j < 4; j++) {
            int d = (nc + j) & 63;
            float e = (float)(2 * (d & 31)) / 64.0f;   // matches jnp arange(0,D,2)/D
            invf[j] = 1.0f / powf(10000.0f, e);
        }
        int h = nc >> 6, d = nc & 63;
        #pragma unroll
        for (int i = 0; i < 4; i++) {
            int m = m0 + (ty << 2) + i;
            int b = m >> 11, s = m & 2047;
            float pos = (float)s;
            float c0 = acc[i][0] + bv4[0];
            float c1 = acc[i][1] + bv4[1];
            float c2 = acc[i][2] + bv4[2];
            float c3 = acc[i][3] + bv4[3];
            float sn[4], cs[4];
            #pragma unroll
            for (int j = 0; j < 4; j++)
                sincos_red(pos * invf[j], &sn[j], &cs[j]);
            float4 o;
            // even d: x[d]*cos - x[d+1]*sin ; odd d: x[d]*cos + x[d-1]*sin
            o.x = c0 * cs[0] - c1 * sn[0];
            o.y = c1 * cs[1] + c0 * sn[1];
            o.z = c2 * cs[2] - c3 * sn[2];
            o.w = c3 * cs[3] + c2 * sn[3];
            *(float4*)&dst[(((size_t)(b * Hv + h) * Sv + s) << 6) + d] = o;
        }
    }
}

// ---------------------------------------------------------------------------
// Causal flash attention, fp32. One CTA = 64 queries of one (b,h).
// 64 threads; each thread owns one query row (q in regs, acc[64] in regs).
// K/V tiles staged in smem; all compute reads are warp-broadcast (conflict-free).
// ---------------------------------------------------------------------------
__global__ __launch_bounds__(64)
void attn_kernel(const float* __restrict__ Q, const float* __restrict__ K,
                 const float* __restrict__ V, float* __restrict__ O)
{
    __shared__ float Ks[64][64];   // [j][d]
    __shared__ float Vs[64][64];   // [j][d]

    int qt = blockIdx.x;           // query tile 0..31
    int bh = blockIdx.y;           // 0..31
    int t  = threadIdx.x;          // query row within tile

    const float* Qb = Q + ((size_t)bh * Sv + qt * 64) * 64;
    const float* Kb = K + (size_t)bh * Sv * 64;
    const float* Vb = V + (size_t)bh * Sv * 64;

    // Own query row in registers, pre-scaled by 1/sqrt(64)
    float q[64];
    #pragma unroll
    for (int d4 = 0; d4 < 64; d4 += 4) {
        float4 v = *(const float4*)&Qb[t * 64 + d4];
        q[d4 + 0] = v.x * 0.125f; q[d4 + 1] = v.y * 0.125f;
        q[d4 + 2] = v.z * 0.125f; q[d4 + 3] = v.w * 0.125f;
    }

    float mrun = -1e30f, lrun = 0.0f;
    float acc[64];
    #pragma unroll
    for (int d = 0; d < 64; d++) acc[d] = 0.0f;

    for (int kt = 0; kt <= qt; kt++) {
        __syncthreads();  // previous tile fully consumed
        // Cooperative, coalesced K/V tile load (conflict-light STS)
        #pragma unroll
        for (int rep = 0; rep < 16; rep++) {
            int j = rep * 4 + (t >> 4);
            int c = (t & 15) << 2;
            *(float4*)&Ks[j][c] = *(const float4*)&Kb[(kt * 64 + j) * 64 + c];
            *(float4*)&Vs[j][c] = *(const float4*)&Vb[(kt * 64 + j) * 64 + c];
        }
        __syncthreads();

        bool diag = (kt == qt);
        float sarr[64];            // per-thread scores (local mem ok)
        float smax = -1e30f;

        #pragma unroll 4
        for (int j = 0; j < 64; j++) {
            float s0 = 0.f, s1 = 0.f, s2 = 0.f, s3 = 0.f;
            const float* kr = &Ks[j][0];
            #pragma unroll
            for (int d4 = 0; d4 < 64; d4 += 4) {
                float4 k4 = *(const float4*)(kr + d4);
                s0 += q[d4 + 0] * k4.x; s1 += q[d4 + 1] * k4.y;
                s2 += q[d4 + 2] * k4.z; s3 += q[d4 + 3] * k4.w;
            }
            float sj = (s0 + s1) + (s2 + s3);
            if (diag && j > t) sj = -1e30f;
            sarr[j] = sj;
            smax = fmaxf(smax, sj);
        }

        float mx = fmaxf(mrun, smax);
        float alpha = __expf(mrun - mx);
        mrun = mx;
        lrun *= alpha;
        #pragma unroll
        for (int d = 0; d < 64; d++) acc[d] *= alpha;

        #pragma unroll 2
        for (int j = 0; j < 64; j++) {
            float pj = __expf(sarr[j] - mx);
            lrun += pj;
            const float* vr = &Vs[j][0];
            #pragma unroll
            for (int d4 = 0; d4 < 64; d4 += 4) {
                float4 v4 = *(const float4*)(vr + d4);
                acc[d4 + 0] += pj * v4.x; acc[d4 + 1] += pj * v4.y;
                acc[d4 + 2] += pj * v4.z; acc[d4 + 3] += pj * v4.w;
            }
        }
    }

    float inv = 1.0f / lrun;
    int b = bh >> 4, h = bh & 15;
    int srow = qt * 64 + t;
    float* dst = O + ((size_t)(b * Sv + srow)) * Ev + h * 64;
    #pragma unroll
    for (int d4 = 0; d4 < 64; d4 += 4) {
        float4 o;
        o.x = acc[d4 + 0] * inv; o.y = acc[d4 + 1] * inv;
        o.z = acc[d4 + 2] * inv; o.w = acc[d4 + 3] * inv;
        *(float4*)&dst[d4] = o;
    }
}

// ---------------------------------------------------------------------------
extern "C" void kernel_launch(void* const* d_in, const int* in_sizes, int n_in,
                              void* d_out, int out_size)
{
    const float* x  = (const float*)d_in[0];
    const float* wq = (const float*)d_in[1];
    const float* bq = (const float*)d_in[2];
    const float* wk = (const float*)d_in[3];
    const float* bk = (const float*)d_in[4];
    const float* wv = (const float*)d_in[5];
    const float* bv = (const float*)d_in[6];
    const float* wo = (const float*)d_in[7];
    const float* bo = (const float*)d_in[8];
    float* out = (float*)d_out;

    float *pQ, *pK, *pV, *pO;
    cudaGetSymbolAddress((void**)&pQ, g_Q);
    cudaGetSymbolAddress((void**)&pK, g_K);
    cudaGetSymbolAddress((void**)&pV, g_V);
    cudaGetSymbolAddress((void**)&pO, g_O);

    dim3 ggrid(Ev / 64, Mtot / 64);   // (16, 64)

    gemm_nt_kernel<<<ggrid, 256>>>(x, wq, bq, pQ, MODE_ROPE);
    gemm_nt_kernel<<<ggrid, 256>>>(x, wk, bk, pK, MODE_ROPE);
    gemm_nt_kernel<<<ggrid, 256>>>(x, wv, bv, pV, MODE_BHSD);

    attn_kernel<<<dim3(Sv / 64, Bv * Hv), 64>>>(pQ, pK, pV, pO);

    gemm_nt_kernel<<<ggrid, 256>>>(pO, wo, bo, out, MODE_PLAIN);
}

// round 5
// speedup vs baseline: 1.4928x; 1.4928x over previous
#include <cuda_runtime.h>
#include <cuda_bf16.h>
#include <cstdint>
#include <math.h>

#define Bv 2
#define Sv 2048
#define Ev 1024
#define Hv 16
#define Dv 64
#define Mtot (Bv * Sv)          // 4096

enum { MODE_ROPE = 0, MODE_BHSD = 1, MODE_PLAIN = 2 };

// ---------------- scratch (__device__ globals; no allocs allowed) ----------
__device__ float g_Q[Bv * Hv * Sv * Dv];
__device__ float g_K[Bv * Hv * Sv * Dv];
__device__ float g_V[Bv * Hv * Sv * Dv];
__device__ float g_O[Mtot * Ev];

__device__ __nv_bfloat16 g_xhi[Mtot * Ev], g_xlo[Mtot * Ev];
__device__ __nv_bfloat16 g_ohi[Mtot * Ev], g_olo[Mtot * Ev];
__device__ __nv_bfloat16 g_wqhi[Ev * Ev], g_wqlo[Ev * Ev];
__device__ __nv_bfloat16 g_wkhi[Ev * Ev], g_wklo[Ev * Ev];
__device__ __nv_bfloat16 g_wvhi[Ev * Ev], g_wvlo[Ev * Ev];
__device__ __nv_bfloat16 g_wohi[Ev * Ev], g_wolo[Ev * Ev];

// ---------------- helpers --------------------------------------------------
__device__ __forceinline__ uint32_t smem_to_u32(const void* p) {
    uint32_t a;
    asm("{ .reg .u64 t; cvta.to.shared.u64 t, %1; cvt.u32.u64 %0, t; }"
        : "=r"(a) : "l"(p));
    return a;
}

__device__ __forceinline__ void ldmatrix_x4(uint32_t* r, uint32_t addr) {
    asm volatile("ldmatrix.sync.aligned.m8n8.x4.shared.b16 {%0,%1,%2,%3}, [%4];"
                 : "=r"(r[0]), "=r"(r[1]), "=r"(r[2]), "=r"(r[3]) : "r"(addr));
}

__device__ __forceinline__ void mma16816(float* c, const uint32_t* a,
                                         const uint32_t* b) {
    asm volatile(
        "mma.sync.aligned.m16n8k16.row.col.f32.bf16.bf16.f32 "
        "{%0,%1,%2,%3}, {%4,%5,%6,%7}, {%8,%9}, {%0,%1,%2,%3};"
        : "+f"(c[0]), "+f"(c[1]), "+f"(c[2]), "+f"(c[3])
        : "r"(a[0]), "r"(a[1]), "r"(a[2]), "r"(a[3]), "r"(b[0]), "r"(b[1]));
}

#define CP_ASYNC16(smem, gptr) \
    asm volatile("cp.async.cg.shared.global [%0], [%1], 16;" \
                 :: "r"(smem), "l"(gptr))
#define CP_COMMIT() asm volatile("cp.async.commit_group;" ::: "memory")
#define CP_WAIT2()  asm volatile("cp.async.wait_group 2;" ::: "memory")

// sincos accurate under --use_fast_math (Cody-Waite 2*pi reduction)
__device__ __forceinline__ void sincos_red(float ang, float* s, float* c) {
    float kf = rintf(ang * 0.15915494309189535f);
    float r = fmaf(kf, -6.2831854820251465f, ang);
    r = fmaf(kf, 1.7484555e-7f, r);
    __sincosf(r, s, c);
}

// ---------------------------------------------------------------------------
// fp32 -> (hi, lo) bf16 split
// ---------------------------------------------------------------------------
__global__ __launch_bounds__(256)
void split_bf16_kernel(const float* __restrict__ src,
                       __nv_bfloat16* __restrict__ hi,
                       __nv_bfloat16* __restrict__ lo)
{
    int i = (blockIdx.x * 256 + threadIdx.x) * 4;
    float4 v = *(const float4*)(src + i);
    __nv_bfloat16 h0 = __float2bfloat16(v.x);
    __nv_bfloat16 h1 = __float2bfloat16(v.y);
    __nv_bfloat16 h2 = __float2bfloat16(v.z);
    __nv_bfloat16 h3 = __float2bfloat16(v.w);
    __nv_bfloat16 l0 = __float2bfloat16(v.x - __bfloat162float(h0));
    __nv_bfloat16 l1 = __float2bfloat16(v.y - __bfloat162float(h1));
    __nv_bfloat16 l2 = __float2bfloat16(v.z - __bfloat162float(h2));
    __nv_bfloat16 l3 = __float2bfloat16(v.w - __bfloat162float(h3));
    __nv_bfloat162 hA; hA.x = h0; hA.y = h1;
    __nv_bfloat162 hB; hB.x = h2; hB.y = h3;
    __nv_bfloat162 lA; lA.x = l0; lA.y = l1;
    __nv_bfloat162 lB; lB.x = l2; lB.y = l3;
    *(__nv_bfloat162*)&hi[i]     = hA;
    *(__nv_bfloat162*)&hi[i + 2] = hB;
    *(__nv_bfloat162*)&lo[i]     = lA;
    *(__nv_bfloat162*)&lo[i + 2] = lB;
}

// ---------------------------------------------------------------------------
// bf16x3 GEMM via mma.sync: C[m,n] = sum_k A[m,k]*W[n,k] + bias[n], K=1024.
// CTA: 128x128 tile, 256 thr (8 warps, 2x4), warp: 64x32.
// Smem tile rows padded to 80 B (5x16B) -> conflict-free ldmatrix.
// ---------------------------------------------------------------------------
#define BK 32
#define NCHUNK (Ev / BK)                 // 32... no: 1024/32 = 32
#define TILEB (128 * 80)                 // 10240 bytes per tile
#define STAGEB (4 * TILEB)               // 40960
#define NSTG 3
#define GEMM_SMEM (NSTG * STAGEB + 256)  // ~123 KB

__global__ __launch_bounds__(256, 1)
void gemm_bf16x3_kernel(const __nv_bfloat16* __restrict__ Ahi,
                        const __nv_bfloat16* __restrict__ Alo,
                        const __nv_bfloat16* __restrict__ Whi,
                        const __nv_bfloat16* __restrict__ Wlo,
                        const float* __restrict__ bias,
                        float* __restrict__ dst, int mode)
{
    extern __shared__ char dsm[];
    uint32_t base = (smem_to_u32(dsm) + 127) & ~127u;

    const int tid = threadIdx.x;
    const int wid = tid >> 5, lid = tid & 31;
    const int wm = wid >> 2, wn = wid & 3;           // warp 2x4 grid
    const int m0 = blockIdx.y * 128, n0 = blockIdx.x * 128;

    const __nv_bfloat16* tsrc[4] = {
        Ahi + (size_t)m0 * Ev, Alo + (size_t)m0 * Ev,
        Whi + (size_t)n0 * Ev, Wlo + (size_t)n0 * Ev };

    const int lr = tid >> 2;          // load row 0..63
    const int lc = tid & 3;           // 16B unit 0..3

    auto load_chunk = [&](int c, int s) {
        const int k0 = c * BK;
        uint32_t sb = base + s * STAGEB;
        #pragma unroll
        for (int tile = 0; tile < 4; tile++) {
            const __nv_bfloat16* sp = tsrc[tile];
            #pragma unroll
            for (int p = 0; p < 2; p++) {
                int row = lr + p * 64;
                uint32_t so = sb + tile * TILEB + row * 80 + lc * 16;
                const void* g = sp + (size_t)row * Ev + k0 + lc * 8;
                CP_ASYNC16(so, g);
            }
        }
    };

    float acc[4][4][4] = {};

    // ldmatrix per-lane offsets
    const uint32_t aoff = (lid & 15) * 80 + (lid >> 4) * 16;
    const uint32_t boff = ((lid >> 4) * 8 + (lid & 7)) * 80 + ((lid >> 3) & 1) * 16;

    #pragma unroll
    for (int s = 0; s < NSTG; s++) { load_chunk(s, s); CP_COMMIT(); }

    for (int c = 0; c < NCHUNK; c++) {
        int s = c % NSTG;
        CP_WAIT2();
        __syncthreads();

        uint32_t sb  = base + s * STAGEB;
        uint32_t aHI = sb + (wm * 64) * 80;
        uint32_t aLO = aHI + TILEB;
        uint32_t bHI = sb + 2 * TILEB + (wn * 32) * 80;
        uint32_t bLO = bHI + TILEB;

        #pragma unroll
        for (int ks = 0; ks < 2; ks++) {
            uint32_t kb = ks * 32;    // 16 halfs = 32 bytes
            uint32_t ah[4][4], al[4][4];
            #pragma unroll
            for (int mt = 0; mt < 4; mt++) {
                ldmatrix_x4(ah[mt], aHI + mt * (16 * 80) + kb + aoff);
                ldmatrix_x4(al[mt], aLO + mt * (16 * 80) + kb + aoff);
            }
            uint32_t bh[4][2], bl[4][2];
            #pragma unroll
            for (int pr = 0; pr < 2; pr++) {
                uint32_t t4[4];
                ldmatrix_x4(t4, bHI + pr * (16 * 80) + kb + boff);
                bh[2 * pr][0] = t4[0]; bh[2 * pr][1] = t4[1];
                bh[2 * pr + 1][0] = t4[2]; bh[2 * pr + 1][1] = t4[3];
                ldmatrix_x4(t4, bLO + pr * (16 * 80) + kb + boff);
                bl[2 * pr][0] = t4[0]; bl[2 * pr][1] = t4[1];
                bl[2 * pr + 1][0] = t4[2]; bl[2 * pr + 1][1] = t4[3];
            }
            #pragma unroll
            for (int mt = 0; mt < 4; mt++)
                #pragma unroll
                for (int nt = 0; nt < 4; nt++) {
                    mma16816(acc[mt][nt], ah[mt], bh[nt]);
                    mma16816(acc[mt][nt], ah[mt], bl[nt]);
                    mma16816(acc[mt][nt], al[mt], bh[nt]);
                }
        }
        __syncthreads();
        if (c + NSTG < NCHUNK) load_chunk(c + NSTG, s);
        CP_COMMIT();
    }

    // ------------------- epilogue -------------------
    const int g4 = lid >> 2, t2 = lid & 3;
    #pragma unroll
    for (int nt = 0; nt < 4; nt++) {
        int n = n0 + wn * 32 + nt * 8 + t2 * 2;
        float bi0 = bias[n], bi1 = bias[n + 1];
        int h = n >> 6, d = n & 63;
        float fe = 0.f, fo = 0.f;
        if (mode == MODE_ROPE) {
            fe = powf(10000.0f, -(float)(2 * (d & 31)) / 64.0f);
            fo = powf(10000.0f, -(float)(2 * ((d + 1) & 31)) / 64.0f);
        }
        #pragma unroll
        for (int mt = 0; mt < 4; mt++) {
            #pragma unroll
            for (int hf = 0; hf < 2; hf++) {
                int m = m0 + wm * 64 + mt * 16 + g4 + hf * 8;
                float v0 = acc[mt][nt][hf * 2 + 0] + bi0;
                float v1 = acc[mt][nt][hf * 2 + 1] + bi1;
                if (mode == MODE_PLAIN) {
                    float2 o = {v0, v1};
                    *(float2*)&dst[(size_t)m * Ev + n] = o;
                } else {
                    int b = m >> 11, srow = m & 2047;
                    if (mode == MODE_ROPE) {
                        float pos = (float)srow;
                        float se, ce, so, co;
                        sincos_red(pos * fe, &se, &ce);
                        sincos_red(pos * fo, &so, &co);
                        float r0 = v0 * ce - v1 * se;
                        float r1 = v1 * co + v0 * so;
                        v0 = r0; v1 = r1;
                    }
                    float2 o = {v0, v1};
                    *(float2*)&dst[(((size_t)(b * Hv + h) * Sv + srow) << 6) + d] = o;
                }
            }
        }
    }
}

// ---------------------------------------------------------------------------
// Causal flash attention, fp32 scalar (unchanged from R1; passes @ 6e-7)
// ---------------------------------------------------------------------------
__global__ __launch_bounds__(64)
void attn_kernel(const float* __restrict__ Q, const float* __restrict__ K,
                 const float* __restrict__ V, float* __restrict__ O)
{
    __shared__ float Ks[64][64];
    __shared__ float Vs[64][64];

    int qt = blockIdx.x;
    int bh = blockIdx.y;
    int t  = threadIdx.x;

    const float* Qb = Q + ((size_t)bh * Sv + qt * 64) * 64;
    const float* Kb = K + (size_t)bh * Sv * 64;
    const float* Vb = V + (size_t)bh * Sv * 64;

    float q[64];
    #pragma unroll
    for (int d4 = 0; d4 < 64; d4 += 4) {
        float4 v = *(const float4*)&Qb[t * 64 + d4];
        q[d4 + 0] = v.x * 0.125f; q[d4 + 1] = v.y * 0.125f;
        q[d4 + 2] = v.z * 0.125f; q[d4 + 3] = v.w * 0.125f;
    }

    float mrun = -1e30f, lrun = 0.0f;
    float acc[64];
    #pragma unroll
    for (int d = 0; d < 64; d++) acc[d] = 0.0f;

    for (int kt = 0; kt <= qt; kt++) {
        __syncthreads();
        #pragma unroll
        for (int rep = 0; rep < 16; rep++) {
            int j = rep * 4 + (t >> 4);
            int c = (t & 15) << 2;
            *(float4*)&Ks[j][c] = *(const float4*)&Kb[(kt * 64 + j) * 64 + c];
            *(float4*)&Vs[j][c] = *(const float4*)&Vb[(kt * 64 + j) * 64 + c];
        }
        __syncthreads();

        bool diag = (kt == qt);
        float sarr[64];
        float smax = -1e30f;

        #pragma unroll 4
        for (int j = 0; j < 64; j++) {
            float s0 = 0.f, s1 = 0.f, s2 = 0.f, s3 = 0.f;
            const float* kr = &Ks[j][0];
            #pragma unroll
            for (int d4 = 0; d4 < 64; d4 += 4) {
                float4 k4 = *(const float4*)(kr + d4);
                s0 += q[d4 + 0] * k4.x; s1 += q[d4 + 1] * k4.y;
                s2 += q[d4 + 2] * k4.z; s3 += q[d4 + 3] * k4.w;
            }
            float sj = (s0 + s1) + (s2 + s3);
            if (diag && j > t) sj = -1e30f;
            sarr[j] = sj;
            smax = fmaxf(smax, sj);
        }

        float mx = fmaxf(mrun, smax);
        float alpha = __expf(mrun - mx);
        mrun = mx;
        lrun *= alpha;
        #pragma unroll
        for (int d = 0; d < 64; d++) acc[d] *= alpha;

        #pragma unroll 2
        for (int j = 0; j < 64; j++) {
            float pj = __expf(sarr[j] - mx);
            lrun += pj;
            const float* vr = &Vs[j][0];
            #pragma unroll
            for (int d4 = 0; d4 < 64; d4 += 4) {
                float4 v4 = *(const float4*)(vr + d4);
                acc[d4 + 0] += pj * v4.x; acc[d4 + 1] += pj * v4.y;
                acc[d4 + 2] += pj * v4.z; acc[d4 + 3] += pj * v4.w;
            }
        }
    }

    float inv = 1.0f / lrun;
    int b = bh >> 4, h = bh & 15;
    int srow = qt * 64 + t;
    float* dst = O + ((size_t)(b * Sv + srow)) * Ev + h * 64;
    #pragma unroll
    for (int d4 = 0; d4 < 64; d4 += 4) {
        float4 o;
        o.x = acc[d4 + 0] * inv; o.y = acc[d4 + 1] * inv;
        o.z = acc[d4 + 2] * inv; o.w = acc[d4 + 3] * inv;
        *(float4*)&dst[d4] = o;
    }
}

// ---------------------------------------------------------------------------
extern "C" void kernel_launch(void* const* d_in, const int* in_sizes, int n_in,
                              void* d_out, int out_size)
{
    const float* x  = (const float*)d_in[0];
    const float* wq = (const float*)d_in[1];
    const float* bq = (const float*)d_in[2];
    const float* wk = (const float*)d_in[3];
    const float* bk = (const float*)d_in[4];
    const float* wv = (const float*)d_in[5];
    const float* bv = (const float*)d_in[6];
    const float* wo = (const float*)d_in[7];
    const float* bo = (const float*)d_in[8];
    float* out = (float*)d_out;

    cudaFuncSetAttribute(gemm_bf16x3_kernel,
                         cudaFuncAttributeMaxDynamicSharedMemorySize, GEMM_SMEM);

    float *pQ, *pK, *pV, *pO;
    cudaGetSymbolAddress((void**)&pQ, g_Q);
    cudaGetSymbolAddress((void**)&pK, g_K);
    cudaGetSymbolAddress((void**)&pV, g_V);
    cudaGetSymbolAddress((void**)&pO, g_O);

    __nv_bfloat16 *xhi, *xlo, *ohi, *olo;
    __nv_bfloat16 *wqhi, *wqlo, *wkhi, *wklo, *wvhi, *wvlo, *wohi, *wolo;
    cudaGetSymbolAddress((void**)&xhi, g_xhi);
    cudaGetSymbolAddress((void**)&xlo, g_xlo);
    cudaGetSymbolAddress((void**)&ohi, g_ohi);
    cudaGetSymbolAddress((void**)&olo, g_olo);
    cudaGetSymbolAddress((void**)&wqhi, g_wqhi);
    cudaGetSymbolAddress((void**)&wqlo, g_wqlo);
    cudaGetSymbolAddress((void**)&wkhi, g_wkhi);
    cudaGetSymbolAddress((void**)&wklo, g_wklo);
    cudaGetSymbolAddress((void**)&wvhi, g_wvhi);
    cudaGetSymbolAddress((void**)&wvlo, g_wvlo);
    cudaGetSymbolAddress((void**)&wohi, g_wohi);
    cudaGetSymbolAddress((void**)&wolo, g_wolo);

    const int NX = Mtot * Ev;   // 4M elements
    const int NW = Ev * Ev;     // 1M elements
    split_bf16_kernel<<<NX / 1024, 256>>>(x,  xhi,  xlo);
    split_bf16_kernel<<<NW / 1024, 256>>>(wq, wqhi, wqlo);
    split_bf16_kernel<<<NW / 1024, 256>>>(wk, wkhi, wklo);
    split_bf16_kernel<<<NW / 1024, 256>>>(wv, wvhi, wvlo);
    split_bf16_kernel<<<NW / 1024, 256>>>(wo, wohi, wolo);

    dim3 ggrid(Ev / 128, Mtot / 128);   // (8, 32)
    gemm_bf16x3_kernel<<<ggrid, 256, GEMM_SMEM>>>(xhi, xlo, wqhi, wqlo, bq, pQ, MODE_ROPE);
    gemm_bf16x3_kernel<<<ggrid, 256, GEMM_SMEM>>>(xhi, xlo, wkhi, wklo, bk, pK, MODE_ROPE);
    gemm_bf16x3_kernel<<<ggrid, 256, GEMM_SMEM>>>(xhi, xlo, wvhi, wvlo, bv, pV, MODE_BHSD);

    attn_kernel<<<dim3(Sv / 64, Bv * Hv), 64>>>(pQ, pK, pV, pO);

    split_bf16_kernel<<<NX / 1024, 256>>>(pO, ohi, olo);
    gemm_bf16x3_kernel<<<ggrid, 256, GEMM_SMEM>>>(ohi, olo, wohi, wolo, bo, out, MODE_PLAIN);
}

// round 6
// speedup vs baseline: 3.3567x; 2.2485x over previous
#include <cuda_runtime.h>
#include <cuda_bf16.h>
#include <cstdint>
#include <math.h>

#define Bv 2
#define Sv 2048
#define Ev 1024
#define Hv 16
#define Dv 64
#define Mtot (Bv * Sv)          // 4096

enum { MODE_ROPEQ = 0, MODE_ROPEK = 1, MODE_BHSD = 2, MODE_PLAIN = 3 };

// ---------------- scratch (__device__ globals; no allocs allowed) ----------
__device__ __nv_bfloat16 g_Qhi[Bv * Hv * Sv * Dv], g_Qlo[Bv * Hv * Sv * Dv];
__device__ __nv_bfloat16 g_Khi[Bv * Hv * Sv * Dv], g_Klo[Bv * Hv * Sv * Dv];
__device__ __nv_bfloat16 g_Vhi[Bv * Hv * Sv * Dv], g_Vlo[Bv * Hv * Sv * Dv];
__device__ __nv_bfloat16 g_xhi[Mtot * Ev], g_xlo[Mtot * Ev];
__device__ __nv_bfloat16 g_ohi[Mtot * Ev], g_olo[Mtot * Ev];
__device__ __nv_bfloat16 g_wqhi[Ev * Ev], g_wqlo[Ev * Ev];
__device__ __nv_bfloat16 g_wkhi[Ev * Ev], g_wklo[Ev * Ev];
__device__ __nv_bfloat16 g_wvhi[Ev * Ev], g_wvlo[Ev * Ev];
__device__ __nv_bfloat16 g_wohi[Ev * Ev], g_wolo[Ev * Ev];

// ---------------- helpers --------------------------------------------------
__device__ __forceinline__ uint32_t smem_to_u32(const void* p) {
    uint32_t a;
    asm("{ .reg .u64 t; cvta.to.shared.u64 t, %1; cvt.u32.u64 %0, t; }"
        : "=r"(a) : "l"(p));
    return a;
}

__device__ __forceinline__ void ldmatrix_x4(uint32_t* r, uint32_t addr) {
    asm volatile("ldmatrix.sync.aligned.m8n8.x4.shared.b16 {%0,%1,%2,%3}, [%4];"
                 : "=r"(r[0]), "=r"(r[1]), "=r"(r[2]), "=r"(r[3]) : "r"(addr));
}
__device__ __forceinline__ void ldmatrix_x4t(uint32_t* r, uint32_t addr) {
    asm volatile("ldmatrix.sync.aligned.m8n8.x4.trans.shared.b16 {%0,%1,%2,%3}, [%4];"
                 : "=r"(r[0]), "=r"(r[1]), "=r"(r[2]), "=r"(r[3]) : "r"(addr));
}

__device__ __forceinline__ void mma16816(float* c, const uint32_t* a,
                                         const uint32_t* b) {
    asm volatile(
        "mma.sync.aligned.m16n8k16.row.col.f32.bf16.bf16.f32 "
        "{%0,%1,%2,%3}, {%4,%5,%6,%7}, {%8,%9}, {%0,%1,%2,%3};"
        : "+f"(c[0]), "+f"(c[1]), "+f"(c[2]), "+f"(c[3])
        : "r"(a[0]), "r"(a[1]), "r"(a[2]), "r"(a[3]), "r"(b[0]), "r"(b[1]));
}

#define CP_ASYNC16(smem, gptr) \
    asm volatile("cp.async.cg.shared.global [%0], [%1], 16;" \
                 :: "r"(smem), "l"(gptr))
#define CP_COMMIT() asm volatile("cp.async.commit_group;" ::: "memory")
#define CP_WAIT2()  asm volatile("cp.async.wait_group 2;" ::: "memory")
#define CP_WAIT1()  asm volatile("cp.async.wait_group 1;" ::: "memory")

// sincos accurate under --use_fast_math (Cody-Waite 2*pi reduction)
__device__ __forceinline__ void sincos_red(float ang, float* s, float* c) {
    float kf = rintf(ang * 0.15915494309189535f);
    float r = fmaf(kf, -6.2831854820251465f, ang);
    r = fmaf(kf, 1.7484555e-7f, r);
    __sincosf(r, s, c);
}

// split two fp32 into packed bf16x2 (hi) + packed bf16x2 (residual lo)
__device__ __forceinline__ void split_pack(float p0, float p1,
                                           uint32_t& hi, uint32_t& lo) {
    __nv_bfloat16 h0 = __float2bfloat16(p0), h1 = __float2bfloat16(p1);
    float r0 = p0 - __bfloat162float(h0), r1 = p1 - __bfloat162float(h1);
    __nv_bfloat162 hp; hp.x = h0; hp.y = h1;
    __nv_bfloat162 lp; lp.x = __float2bfloat16(r0); lp.y = __float2bfloat16(r1);
    hi = *(uint32_t*)&hp; lo = *(uint32_t*)&lp;
}

// ---------------------------------------------------------------------------
// fp32 -> (hi, lo) bf16 split (bulk)
// ---------------------------------------------------------------------------
__global__ __launch_bounds__(256)
void split_bf16_kernel(const float* __restrict__ src,
                       __nv_bfloat16* __restrict__ hi,
                       __nv_bfloat16* __restrict__ lo)
{
    int i = (blockIdx.x * 256 + threadIdx.x) * 4;
    float4 v = *(const float4*)(src + i);
    uint32_t hA, lA, hB, lB;
    split_pack(v.x, v.y, hA, lA);
    split_pack(v.z, v.w, hB, lB);
    *(uint32_t*)&hi[i]     = hA;
    *(uint32_t*)&hi[i + 2] = hB;
    *(uint32_t*)&lo[i]     = lA;
    *(uint32_t*)&lo[i + 2] = lB;
}

// ---------------------------------------------------------------------------
// bf16x3 GEMM via mma.sync: C[m,n] = sum_k A[m,k]*W[n,k] + bias[n], K=1024.
// CTA: 128x128 tile, 8 warps (2x4), warp 64x32. Rows padded to 80B.
// Epilogue: PLAIN -> f32; ROPEQ/ROPEK/BHSD -> bf16 hi/lo [B,H,S,D].
// ---------------------------------------------------------------------------
#define BK 32
#define NCHUNK (Ev / BK)
#define TILEB (128 * 80)
#define STAGEB (4 * TILEB)
#define NSTG 3
#define GEMM_SMEM (NSTG * STAGEB + 256)

__global__ __launch_bounds__(256, 1)
void gemm_bf16x3_kernel(const __nv_bfloat16* __restrict__ Ahi,
                        const __nv_bfloat16* __restrict__ Alo,
                        const __nv_bfloat16* __restrict__ Whi,
                        const __nv_bfloat16* __restrict__ Wlo,
                        const float* __restrict__ bias,
                        float* __restrict__ dstf,
                        __nv_bfloat16* __restrict__ dsthi,
                        __nv_bfloat16* __restrict__ dstlo, int mode)
{
    extern __shared__ char dsm[];
    uint32_t base = (smem_to_u32(dsm) + 127) & ~127u;

    const int tid = threadIdx.x;
    const int wid = tid >> 5, lid = tid & 31;
    const int wm = wid >> 2, wn = wid & 3;
    const int m0 = blockIdx.y * 128, n0 = blockIdx.x * 128;

    const __nv_bfloat16* tsrc[4] = {
        Ahi + (size_t)m0 * Ev, Alo + (size_t)m0 * Ev,
        Whi + (size_t)n0 * Ev, Wlo + (size_t)n0 * Ev };

    const int lr = tid >> 2;
    const int lc = tid & 3;

    auto load_chunk = [&](int c, int s) {
        const int k0 = c * BK;
        uint32_t sb = base + s * STAGEB;
        #pragma unroll
        for (int tile = 0; tile < 4; tile++) {
            const __nv_bfloat16* sp = tsrc[tile];
            #pragma unroll
            for (int p = 0; p < 2; p++) {
                int row = lr + p * 64;
                uint32_t so = sb + tile * TILEB + row * 80 + lc * 16;
                const void* g = sp + (size_t)row * Ev + k0 + lc * 8;
                CP_ASYNC16(so, g);
            }
        }
    };

    float acc[4][4][4] = {};

    const uint32_t aoff = (lid & 15) * 80 + (lid >> 4) * 16;
    const uint32_t boff = ((lid >> 4) * 8 + (lid & 7)) * 80 + ((lid >> 3) & 1) * 16;

    #pragma unroll
    for (int s = 0; s < NSTG; s++) { load_chunk(s, s); CP_COMMIT(); }

    for (int c = 0; c < NCHUNK; c++) {
        int s = c % NSTG;
        CP_WAIT2();
        __syncthreads();

        uint32_t sb  = base + s * STAGEB;
        uint32_t aHI = sb + (wm * 64) * 80;
        uint32_t aLO = aHI + TILEB;
        uint32_t bHI = sb + 2 * TILEB + (wn * 32) * 80;
        uint32_t bLO = bHI + TILEB;

        #pragma unroll
        for (int ks = 0; ks < 2; ks++) {
            uint32_t kb = ks * 32;
            uint32_t ah[4][4], al[4][4];
            #pragma unroll
            for (int mt = 0; mt < 4; mt++) {
                ldmatrix_x4(ah[mt], aHI + mt * (16 * 80) + kb + aoff);
                ldmatrix_x4(al[mt], aLO + mt * (16 * 80) + kb + aoff);
            }
            uint32_t bh[4][2], bl[4][2];
            #pragma unroll
            for (int pr = 0; pr < 2; pr++) {
                uint32_t t4[4];
                ldmatrix_x4(t4, bHI + pr * (16 * 80) + kb + boff);
                bh[2 * pr][0] = t4[0]; bh[2 * pr][1] = t4[1];
                bh[2 * pr + 1][0] = t4[2]; bh[2 * pr + 1][1] = t4[3];
                ldmatrix_x4(t4, bLO + pr * (16 * 80) + kb + boff);
                bl[2 * pr][0] = t4[0]; bl[2 * pr][1] = t4[1];
                bl[2 * pr + 1][0] = t4[2]; bl[2 * pr + 1][1] = t4[3];
            }
            #pragma unroll
            for (int mt = 0; mt < 4; mt++)
                #pragma unroll
                for (int nt = 0; nt < 4; nt++) {
                    mma16816(acc[mt][nt], ah[mt], bh[nt]);
                    mma16816(acc[mt][nt], ah[mt], bl[nt]);
                    mma16816(acc[mt][nt], al[mt], bh[nt]);
                }
        }
        __syncthreads();
        if (c + NSTG < NCHUNK) load_chunk(c + NSTG, s);
        CP_COMMIT();
    }

    // ------------------- epilogue -------------------
    const int g4 = lid >> 2, t2 = lid & 3;
    #pragma unroll
    for (int nt = 0; nt < 4; nt++) {
        int n = n0 + wn * 32 + nt * 8 + t2 * 2;
        float bi0 = bias[n], bi1 = bias[n + 1];
        int h = n >> 6, d = n & 63;
        float fe = 0.f, fo = 0.f;
        if (mode == MODE_ROPEQ || mode == MODE_ROPEK) {
            fe = powf(10000.0f, -(float)(2 * (d & 31)) / 64.0f);
            fo = powf(10000.0f, -(float)(2 * ((d + 1) & 31)) / 64.0f);
        }
        #pragma unroll
        for (int mt = 0; mt < 4; mt++) {
            #pragma unroll
            for (int hf = 0; hf < 2; hf++) {
                int m = m0 + wm * 64 + mt * 16 + g4 + hf * 8;
                float v0 = acc[mt][nt][hf * 2 + 0] + bi0;
                float v1 = acc[mt][nt][hf * 2 + 1] + bi1;
                if (mode == MODE_PLAIN) {
                    float2 o = {v0, v1};
                    *(float2*)&dstf[(size_t)m * Ev + n] = o;
                } else {
                    int b = m >> 11, srow = m & 2047;
                    if (mode != MODE_BHSD) {
                        float pos = (float)srow;
                        float se, ce, so, co;
                        sincos_red(pos * fe, &se, &ce);
                        sincos_red(pos * fo, &so, &co);
                        float r0 = v0 * ce - v1 * se;
                        float r1 = v1 * co + v0 * so;
                        v0 = r0; v1 = r1;
                        if (mode == MODE_ROPEQ) { v0 *= 0.125f; v1 *= 0.125f; }
                    }
                    uint32_t hw, lw;
                    split_pack(v0, v1, hw, lw);
                    size_t off = (((size_t)(b * Hv + h) * Sv + srow) << 6) + d;
                    *(uint32_t*)&dsthi[off] = hw;
                    *(uint32_t*)&dstlo[off] = lw;
                }
            }
        }
    }
}

// ---------------------------------------------------------------------------
// Flash attention via mma.sync, bf16x3. CTA = 128 queries of one (b,h).
// 8 warps x 16 query rows. K-tiles of 64, double-buffered cp.async.
// Smem rows padded to 144B (9x16B) -> conflict-free ldmatrix.
// Output written as bf16 hi/lo into [M, E] (feeds final GEMM directly).
// ---------------------------------------------------------------------------
#define PITCHB 144
#define QSMB (128 * PITCHB)          // 18432
#define KVTILE (64 * PITCHB)         // 9216
#define KVSTG (4 * KVTILE)           // 36864
#define ATTN_SMEM (2 * QSMB + 2 * KVSTG)   // 110592

__global__ __launch_bounds__(256, 1)
void attn_mma_kernel(const __nv_bfloat16* __restrict__ Qhi,
                     const __nv_bfloat16* __restrict__ Qlo,
                     const __nv_bfloat16* __restrict__ Khi,
                     const __nv_bfloat16* __restrict__ Klo,
                     const __nv_bfloat16* __restrict__ Vhi,
                     const __nv_bfloat16* __restrict__ Vlo,
                     __nv_bfloat16* __restrict__ Ohi,
                     __nv_bfloat16* __restrict__ Olo)
{
    extern __shared__ char dsm[];
    uint32_t base = smem_to_u32(dsm);
    const int tid = threadIdx.x, wid = tid >> 5, lid = tid & 31;
    const int qt = (int)gridDim.x - 1 - (int)blockIdx.x;  // longest first
    const int bh = blockIdx.y;
    const int nkt = 2 * (qt + 1);
    const size_t bhb = (size_t)bh * Sv * 64;

    const uint32_t qhib = base, qlob = base + QSMB;
    const uint32_t stg = base + 2 * QSMB;

    auto load_kv = [&](int kt, int s) {
        uint32_t sb = stg + s * KVSTG;
        const __nv_bfloat16* srcs[4] = {
            Khi + bhb + (size_t)kt * 64 * 64, Klo + bhb + (size_t)kt * 64 * 64,
            Vhi + bhb + (size_t)kt * 64 * 64, Vlo + bhb + (size_t)kt * 64 * 64 };
        #pragma unroll
        for (int it = 0; it < 8; it++) {
            int e = it * 256 + tid;
            int tl = e >> 9, r = (e >> 3) & 63, ch = e & 7;
            CP_ASYNC16(sb + tl * KVTILE + r * PITCHB + ch * 16,
                       srcs[tl] + r * 64 + ch * 8);
        }
    };

    // prologue: Q + stage0 as group0; stage1 as group1
    {
        const __nv_bfloat16* gh = Qhi + bhb + (size_t)qt * 128 * 64;
        const __nv_bfloat16* gl = Qlo + bhb + (size_t)qt * 128 * 64;
        #pragma unroll
        for (int it = 0; it < 4; it++) {
            int e = it * 256 + tid;
            int r = e >> 3, ch = e & 7;
            CP_ASYNC16(qhib + r * PITCHB + ch * 16, gh + r * 64 + ch * 8);
            CP_ASYNC16(qlob + r * PITCHB + ch * 16, gl + r * 64 + ch * 8);
        }
        load_kv(0, 0);
        CP_COMMIT();
        load_kv(1, 1);
        CP_COMMIT();
    }
    CP_WAIT1();
    __syncthreads();

    // Q fragments (register resident for whole kernel)
    uint32_t qfh[4][4], qfl[4][4];
    {
        uint32_t qfo = (wid * 16 + (lid & 15)) * PITCHB + (lid >> 4) * 16;
        #pragma unroll
        for (int kc = 0; kc < 4; kc++) {
            ldmatrix_x4(qfh[kc], qhib + qfo + kc * 32);
            ldmatrix_x4(qfl[kc], qlob + qfo + kc * 32);
        }
    }

    float m0 = -1e30f, m1 = -1e30f, l0 = 0.f, l1 = 0.f;
    float accO[8][4] = {};

    const uint32_t kfo = ((lid >> 4) * 8 + (lid & 7)) * PITCHB + ((lid >> 3) & 1) * 16;
    const uint32_t vfo = (lid & 15) * PITCHB + (lid >> 4) * 16;
    const int g4 = lid >> 2, t2 = lid & 3;

    for (int kt = 0; kt < nkt; kt++) {
        uint32_t sb = stg + (kt & 1) * KVSTG;

        // ---- S = Q K^T (bf16x3) ----
        float S[8][4] = {};
        #pragma unroll
        for (int kc = 0; kc < 4; kc++) {
            #pragma unroll
            for (int n0t = 0; n0t < 4; n0t++) {
                uint32_t ka = sb + (n0t * 16) * PITCHB + kc * 32 + kfo;
                uint32_t kh[4], kl[4];
                ldmatrix_x4(kh, ka);
                ldmatrix_x4(kl, ka + KVTILE);
                mma16816(S[2 * n0t], qfh[kc], kh);
                mma16816(S[2 * n0t], qfh[kc], kl);
                mma16816(S[2 * n0t], qfl[kc], kh);
                mma16816(S[2 * n0t + 1], qfh[kc], kh + 2);
                mma16816(S[2 * n0t + 1], qfh[kc], kl + 2);
                mma16816(S[2 * n0t + 1], qfl[kc], kh + 2);
            }
        }

        // ---- causal mask (only last two k-tiles) ----
        if (kt >= 2 * qt) {
            int j0g = kt * 64, q0g = qt * 128 + wid * 16;
            int colb = t2 * 2, rowb = g4;
            #pragma unroll
            for (int nt = 0; nt < 8; nt++) {
                int jb = j0g + nt * 8 + colb;
                if (jb > q0g + rowb)          S[nt][0] = -1e30f;
                if (jb + 1 > q0g + rowb)      S[nt][1] = -1e30f;
                if (jb > q0g + rowb + 8)      S[nt][2] = -1e30f;
                if (jb + 1 > q0g + rowb + 8)  S[nt][3] = -1e30f;
            }
        }

        // ---- online softmax ----
        float mx0 = -1e30f, mx1 = -1e30f;
        #pragma unroll
        for (int nt = 0; nt < 8; nt++) {
            mx0 = fmaxf(mx0, fmaxf(S[nt][0], S[nt][1]));
            mx1 = fmaxf(mx1, fmaxf(S[nt][2], S[nt][3]));
        }
        mx0 = fmaxf(mx0, __shfl_xor_sync(0xffffffffu, mx0, 1));
        mx0 = fmaxf(mx0, __shfl_xor_sync(0xffffffffu, mx0, 2));
        mx1 = fmaxf(mx1, __shfl_xor_sync(0xffffffffu, mx1, 1));
        mx1 = fmaxf(mx1, __shfl_xor_sync(0xffffffffu, mx1, 2));
        float nm0 = fmaxf(m0, mx0), nm1 = fmaxf(m1, mx1);
        float a0 = __expf(m0 - nm0), a1 = __expf(m1 - nm1);
        m0 = nm0; m1 = nm1;

        float rs0 = 0.f, rs1 = 0.f;
        uint32_t phA[8], phB[8], plA[8], plB[8];   // rowlo/rowhi packed pairs
        #pragma unroll
        for (int nt = 0; nt < 8; nt++) {
            float p0 = __expf(S[nt][0] - nm0), p1 = __expf(S[nt][1] - nm0);
            float p2 = __expf(S[nt][2] - nm1), p3 = __expf(S[nt][3] - nm1);
            rs0 += p0 + p1; rs1 += p2 + p3;
            split_pack(p0, p1, phA[nt], plA[nt]);
            split_pack(p2, p3, phB[nt], plB[nt]);
        }
        rs0 += __shfl_xor_sync(0xffffffffu, rs0, 1);
        rs0 += __shfl_xor_sync(0xffffffffu, rs0, 2);
        rs1 += __shfl_xor_sync(0xffffffffu, rs1, 1);
        rs1 += __shfl_xor_sync(0xffffffffu, rs1, 2);
        l0 = l0 * a0 + rs0;
        l1 = l1 * a1 + rs1;
        #pragma unroll
        for (int dt = 0; dt < 8; dt++) {
            accO[dt][0] *= a0; accO[dt][1] *= a0;
            accO[dt][2] *= a1; accO[dt][3] *= a1;
        }

        // ---- O += P V (bf16x3) ----
        uint32_t vb = sb + 2 * KVTILE;
        #pragma unroll
        for (int kc = 0; kc < 4; kc++) {
            uint32_t aph[4] = {phA[2 * kc], phB[2 * kc], phA[2 * kc + 1], phB[2 * kc + 1]};
            uint32_t apl[4] = {plA[2 * kc], plB[2 * kc], plA[2 * kc + 1], plB[2 * kc + 1]};
            #pragma unroll
            for (int d0t = 0; d0t < 4; d0t++) {
                uint32_t va = vb + (kc * 16) * PITCHB + d0t * 32 + vfo;
                uint32_t vh[4], vl[4];
                ldmatrix_x4t(vh, va);
                ldmatrix_x4t(vl, va + KVTILE);
                mma16816(accO[2 * d0t], aph, vh);
                mma16816(accO[2 * d0t], apl, vh);
                mma16816(accO[2 * d0t], aph, vl);
                mma16816(accO[2 * d0t + 1], aph, vh + 2);
                mma16816(accO[2 * d0t + 1], apl, vh + 2);
                mma16816(accO[2 * d0t + 1], aph, vl + 2);
            }
        }

        __syncthreads();                 // stage (kt&1) fully consumed
        if (kt + 2 < nkt) load_kv(kt + 2, kt & 1);
        CP_COMMIT();
        CP_WAIT1();
        __syncthreads();                 // stage (kt+1)&1 ready
    }

    // ---- epilogue: normalize, split to bf16 hi/lo, write [M, E] ----
    float inv0 = 1.0f / l0, inv1 = 1.0f / l1;
    int b = bh >> 4, h = bh & 15;
    int s0 = qt * 128 + wid * 16 + g4, s1 = s0 + 8;
    size_t r0o = ((size_t)(b * Sv + s0)) * Ev + h * 64;
    size_t r1o = ((size_t)(b * Sv + s1)) * Ev + h * 64;
    #pragma unroll
    for (int dt = 0; dt < 8; dt++) {
        int d = dt * 8 + t2 * 2;
        uint32_t hw, lw;
        split_pack(accO[dt][0] * inv0, accO[dt][1] * inv0, hw, lw);
        *(uint32_t*)&Ohi[r0o + d] = hw;
        *(uint32_t*)&Olo[r0o + d] = lw;
        split_pack(accO[dt][2] * inv1, accO[dt][3] * inv1, hw, lw);
        *(uint32_t*)&Ohi[r1o + d] = hw;
        *(uint32_t*)&Olo[r1o + d] = lw;
    }
}

// ---------------------------------------------------------------------------
extern "C" void kernel_launch(void* const* d_in, const int* in_sizes, int n_in,
                              void* d_out, int out_size)
{
    const float* x  = (const float*)d_in[0];
    const float* wq = (const float*)d_in[1];
    const float* bq = (const float*)d_in[2];
    const float* wk = (const float*)d_in[3];
    const float* bk = (const float*)d_in[4];
    const float* wv = (const float*)d_in[5];
    const float* bv = (const float*)d_in[6];
    const float* wo = (const float*)d_in[7];
    const float* bo = (const float*)d_in[8];
    float* out = (float*)d_out;

    cudaFuncSetAttribute(gemm_bf16x3_kernel,
                         cudaFuncAttributeMaxDynamicSharedMemorySize, GEMM_SMEM);
    cudaFuncSetAttribute(attn_mma_kernel,
                         cudaFuncAttributeMaxDynamicSharedMemorySize, ATTN_SMEM);

    __nv_bfloat16 *qhi, *qlo, *khi, *klo, *vhi, *vlo;
    __nv_bfloat16 *xhi, *xlo, *ohi, *olo;
    __nv_bfloat16 *wqhi, *wqlo, *wkhi, *wklo, *wvhi, *wvlo, *wohi, *wolo;
    cudaGetSymbolAddress((void**)&qhi, g_Qhi);
    cudaGetSymbolAddress((void**)&qlo, g_Qlo);
    cudaGetSymbolAddress((void**)&khi, g_Khi);
    cudaGetSymbolAddress((void**)&klo, g_Klo);
    cudaGetSymbolAddress((void**)&vhi, g_Vhi);
    cudaGetSymbolAddress((void**)&vlo, g_Vlo);
    cudaGetSymbolAddress((void**)&xhi, g_xhi);
    cudaGetSymbolAddress((void**)&xlo, g_xlo);
    cudaGetSymbolAddress((void**)&ohi, g_ohi);
    cudaGetSymbolAddress((void**)&olo, g_olo);
    cudaGetSymbolAddress((void**)&wqhi, g_wqhi);
    cudaGetSymbolAddress((void**)&wqlo, g_wqlo);
    cudaGetSymbolAddress((void**)&wkhi, g_wkhi);
    cudaGetSymbolAddress((void**)&wklo, g_wklo);
    cudaGetSymbolAddress((void**)&wvhi, g_wvhi);
    cudaGetSymbolAddress((void**)&wvlo, g_wvlo);
    cudaGetSymbolAddress((void**)&wohi, g_wohi);
    cudaGetSymbolAddress((void**)&wolo, g_wolo);

    const int NX = Mtot * Ev;
    const int NW = Ev * Ev;
    split_bf16_kernel<<<NX / 1024, 256>>>(x,  xhi,  xlo);
    split_bf16_kernel<<<NW / 1024, 256>>>(wq, wqhi, wqlo);
    split_bf16_kernel<<<NW / 1024, 256>>>(wk, wkhi, wklo);
    split_bf16_kernel<<<NW / 1024, 256>>>(wv, wvhi, wvlo);
    split_bf16_kernel<<<NW / 1024, 256>>>(wo, wohi, wolo);

    dim3 ggrid(Ev / 128, Mtot / 128);   // (8, 32)
    gemm_bf16x3_kernel<<<ggrid, 256, GEMM_SMEM>>>(
        xhi, xlo, wqhi, wqlo, bq, nullptr, qhi, qlo, MODE_ROPEQ);
    gemm_bf16x3_kernel<<<ggrid, 256, GEMM_SMEM>>>(
        xhi, xlo, wkhi, wklo, bk, nullptr, khi, klo, MODE_ROPEK);
    gemm_bf16x3_kernel<<<ggrid, 256, GEMM_SMEM>>>(
        xhi, xlo, wvhi, wvlo, bv, nullptr, vhi, vlo, MODE_BHSD);

    attn_mma_kernel<<<dim3(Sv / 128, Bv * Hv), 256, ATTN_SMEM>>>(
        qhi, qlo, khi, klo, vhi, vlo, ohi, olo);

    gemm_bf16x3_kernel<<<ggrid, 256, GEMM_SMEM>>>(
        ohi, olo, wohi, wolo, bo, out, nullptr, nullptr, MODE_PLAIN);
}

// round 7
// speedup vs baseline: 3.6853x; 1.0979x over previous
#include <cuda_runtime.h>
#include <cuda_bf16.h>
#include <cstdint>
#include <math.h>

#define Bv 2
#define Sv 2048
#define Ev 1024
#define Hv 16
#define Dv 64
#define Mtot (Bv * Sv)          // 4096

enum { MODE_ROPEQ = 0, MODE_ROPEK = 1, MODE_BHSD = 2, MODE_PLAIN = 3 };

// ---------------- scratch (__device__ globals; no allocs allowed) ----------
__device__ __nv_bfloat16 g_Qhi[Bv * Hv * Sv * Dv], g_Qlo[Bv * Hv * Sv * Dv];
__device__ __nv_bfloat16 g_Khi[Bv * Hv * Sv * Dv], g_Klo[Bv * Hv * Sv * Dv];
__device__ __nv_bfloat16 g_Vhi[Bv * Hv * Sv * Dv], g_Vlo[Bv * Hv * Sv * Dv];
__device__ __nv_bfloat16 g_xhi[Mtot * Ev], g_xlo[Mtot * Ev];
__device__ __nv_bfloat16 g_ohi[Mtot * Ev], g_olo[Mtot * Ev];
__device__ __nv_bfloat16 g_wqhi[Ev * Ev], g_wqlo[Ev * Ev];
__device__ __nv_bfloat16 g_wkhi[Ev * Ev], g_wklo[Ev * Ev];
__device__ __nv_bfloat16 g_wvhi[Ev * Ev], g_wvlo[Ev * Ev];
__device__ __nv_bfloat16 g_wohi[Ev * Ev], g_wolo[Ev * Ev];

// ---------------- helpers --------------------------------------------------
__device__ __forceinline__ uint32_t smem_to_u32(const void* p) {
    uint32_t a;
    asm("{ .reg .u64 t; cvta.to.shared.u64 t, %1; cvt.u32.u64 %0, t; }"
        : "=r"(a) : "l"(p));
    return a;
}

__device__ __forceinline__ void ldmatrix_x4(uint32_t* r, uint32_t addr) {
    asm volatile("ldmatrix.sync.aligned.m8n8.x4.shared.b16 {%0,%1,%2,%3}, [%4];"
                 : "=r"(r[0]), "=r"(r[1]), "=r"(r[2]), "=r"(r[3]) : "r"(addr));
}
__device__ __forceinline__ void ldmatrix_x4t(uint32_t* r, uint32_t addr) {
    asm volatile("ldmatrix.sync.aligned.m8n8.x4.trans.shared.b16 {%0,%1,%2,%3}, [%4];"
                 : "=r"(r[0]), "=r"(r[1]), "=r"(r[2]), "=r"(r[3]) : "r"(addr));
}

__device__ __forceinline__ void mma16816(float* c, const uint32_t* a,
                                         const uint32_t* b) {
    asm volatile(
        "mma.sync.aligned.m16n8k16.row.col.f32.bf16.bf16.f32 "
        "{%0,%1,%2,%3}, {%4,%5,%6,%7}, {%8,%9}, {%0,%1,%2,%3};"
        : "+f"(c[0]), "+f"(c[1]), "+f"(c[2]), "+f"(c[3])
        : "r"(a[0]), "r"(a[1]), "r"(a[2]), "r"(a[3]), "r"(b[0]), "r"(b[1]));
}

#define CP_ASYNC16(smem, gptr) \
    asm volatile("cp.async.cg.shared.global [%0], [%1], 16;" \
                 :: "r"(smem), "l"(gptr))
#define CP_COMMIT() asm volatile("cp.async.commit_group;" ::: "memory")
#define CP_WAIT2()  asm volatile("cp.async.wait_group 2;" ::: "memory")
#define CP_WAIT1()  asm volatile("cp.async.wait_group 1;" ::: "memory")

// sincos accurate under --use_fast_math (Cody-Waite 2*pi reduction)
__device__ __forceinline__ void sincos_red(float ang, float* s, float* c) {
    float kf = rintf(ang * 0.15915494309189535f);
    float r = fmaf(kf, -6.2831854820251465f, ang);
    r = fmaf(kf, 1.7484555e-7f, r);
    __sincosf(r, s, c);
}

// split two fp32 into packed bf16x2 (hi) + packed bf16x2 (residual lo)
__device__ __forceinline__ void split_pack(float p0, float p1,
                                           uint32_t& hi, uint32_t& lo) {
    __nv_bfloat16 h0 = __float2bfloat16(p0), h1 = __float2bfloat16(p1);
    float r0 = p0 - __bfloat162float(h0), r1 = p1 - __bfloat162float(h1);
    __nv_bfloat162 hp; hp.x = h0; hp.y = h1;
    __nv_bfloat162 lp; lp.x = __float2bfloat16(r0); lp.y = __float2bfloat16(r1);
    hi = *(uint32_t*)&hp; lo = *(uint32_t*)&lp;
}

// ---------------------------------------------------------------------------
// fp32 -> (hi, lo) bf16 splits
// ---------------------------------------------------------------------------
__global__ __launch_bounds__(256)
void split_bf16_kernel(const float* __restrict__ src,
                       __nv_bfloat16* __restrict__ hi,
                       __nv_bfloat16* __restrict__ lo)
{
    int i = (blockIdx.x * 256 + threadIdx.x) * 4;
    float4 v = *(const float4*)(src + i);
    uint32_t hA, lA, hB, lB;
    split_pack(v.x, v.y, hA, lA);
    split_pack(v.z, v.w, hB, lB);
    *(uint32_t*)&hi[i]     = hA;
    *(uint32_t*)&hi[i + 2] = hB;
    *(uint32_t*)&lo[i]     = lA;
    *(uint32_t*)&lo[i + 2] = lB;
}

// fused split of the 4 weight matrices (one launch)
__global__ __launch_bounds__(256)
void split4_kernel(const float* __restrict__ w0, const float* __restrict__ w1,
                   const float* __restrict__ w2, const float* __restrict__ w3,
                   __nv_bfloat16* __restrict__ h0, __nv_bfloat16* __restrict__ l0,
                   __nv_bfloat16* __restrict__ h1, __nv_bfloat16* __restrict__ l1,
                   __nv_bfloat16* __restrict__ h2, __nv_bfloat16* __restrict__ l2,
                   __nv_bfloat16* __restrict__ h3, __nv_bfloat16* __restrict__ l3)
{
    int y = blockIdx.y;
    const float* src = (y == 0) ? w0 : (y == 1) ? w1 : (y == 2) ? w2 : w3;
    __nv_bfloat16* hi = (y == 0) ? h0 : (y == 1) ? h1 : (y == 2) ? h2 : h3;
    __nv_bfloat16* lo = (y == 0) ? l0 : (y == 1) ? l1 : (y == 2) ? l2 : l3;
    int i = (blockIdx.x * 256 + threadIdx.x) * 4;
    float4 v = *(const float4*)(src + i);
    uint32_t hA, lA, hB, lB;
    split_pack(v.x, v.y, hA, lA);
    split_pack(v.z, v.w, hB, lB);
    *(uint32_t*)&hi[i]     = hA;
    *(uint32_t*)&hi[i + 2] = hB;
    *(uint32_t*)&lo[i]     = lA;
    *(uint32_t*)&lo[i + 2] = lB;
}

// ---------------------------------------------------------------------------
// bf16x3 GEMM core via mma.sync: C[m,n] = sum_k A[m,k]*W[n,k] + bias[n].
// CTA: 128(M) x 256(N), 8 warps (2x4), warp tile 64x64. K-chunks of 32.
// Rows padded to 80B -> conflict-free ldmatrix. 3-stage cp.async pipeline.
// ---------------------------------------------------------------------------
#define GBK 32
#define GNCHUNK (Ev / GBK)               // 32
#define ATB (128 * 80)                   // 10240  (A tile: hi or lo)
#define WTB (256 * 80)                   // 20480  (W tile: hi or lo)
#define STAGEB (2 * ATB + 2 * WTB)       // 61440
#define NSTG 3
#define GEMM_SMEM (NSTG * STAGEB + 256)  // 184576

__device__ __forceinline__
void gemm_core(const __nv_bfloat16* __restrict__ Ahi,
               const __nv_bfloat16* __restrict__ Alo,
               const __nv_bfloat16* __restrict__ Whi,
               const __nv_bfloat16* __restrict__ Wlo,
               const float* __restrict__ bias,
               float* __restrict__ dstf,
               __nv_bfloat16* __restrict__ dsthi,
               __nv_bfloat16* __restrict__ dstlo, int mode)
{
    extern __shared__ char dsm[];
    uint32_t base = (smem_to_u32(dsm) + 127) & ~127u;

    const int tid = threadIdx.x;
    const int wid = tid >> 5, lid = tid & 31;
    const int wm = wid >> 2, wn = wid & 3;       // 2x4 warp grid
    const int m0 = blockIdx.y * 128, n0 = blockIdx.x * 256;

    const __nv_bfloat16* Aho = Ahi + (size_t)m0 * Ev;
    const __nv_bfloat16* Alo2 = Alo + (size_t)m0 * Ev;
    const __nv_bfloat16* Who = Whi + (size_t)n0 * Ev;
    const __nv_bfloat16* Wlo2 = Wlo + (size_t)n0 * Ev;

    auto load_chunk = [&](int c, int s) {
        const int k0 = c * GBK;
        uint32_t sb = base + s * STAGEB;
        #pragma unroll
        for (int it = 0; it < 12; it++) {
            int e = it * 256 + tid;
            int c16 = e & 3;
            int grow = e >> 2;                  // 0..767
            uint32_t so;
            const __nv_bfloat16* g;
            if (grow < 256) {                   // A tiles
                int sub = grow >> 7, row = grow & 127;
                so = sb + sub * ATB + row * 80 + c16 * 16;
                g = (sub ? Alo2 : Aho) + (size_t)row * Ev + k0 + c16 * 8;
            } else {                            // W tiles
                int gw = grow - 256;
                int sub = gw >> 8, row = gw & 255;
                so = sb + 2 * ATB + sub * WTB + row * 80 + c16 * 16;
                g = (sub ? Wlo2 : Who) + (size_t)row * Ev + k0 + c16 * 8;
            }
            CP_ASYNC16(so, g);
        }
    };

    float acc[4][8][4] = {};

    const uint32_t aoff = (lid & 15) * 80 + (lid >> 4) * 16;
    const uint32_t boff = ((lid >> 4) * 8 + (lid & 7)) * 80 + ((lid >> 3) & 1) * 16;

    #pragma unroll
    for (int s = 0; s < NSTG; s++) { load_chunk(s, s); CP_COMMIT(); }

    for (int c = 0; c < GNCHUNK; c++) {
        int s = c % NSTG;
        CP_WAIT2();
        __syncthreads();

        uint32_t sb  = base + s * STAGEB;
        uint32_t aHI = sb + (wm * 64) * 80;
        uint32_t aLO = aHI + ATB;
        uint32_t bHI = sb + 2 * ATB + (wn * 64) * 80;
        uint32_t bLO = bHI + WTB;

        #pragma unroll
        for (int ks = 0; ks < 2; ks++) {
            uint32_t kb = ks * 32;
            uint32_t ah[4][4], al[4][4];
            #pragma unroll
            for (int mt = 0; mt < 4; mt++) {
                ldmatrix_x4(ah[mt], aHI + mt * (16 * 80) + kb + aoff);
                ldmatrix_x4(al[mt], aLO + mt * (16 * 80) + kb + aoff);
            }
            uint32_t bh[8][2], bl[8][2];
            #pragma unroll
            for (int pr = 0; pr < 4; pr++) {
                uint32_t t4[4];
                ldmatrix_x4(t4, bHI + pr * (16 * 80) + kb + boff);
                bh[2 * pr][0] = t4[0]; bh[2 * pr][1] = t4[1];
                bh[2 * pr + 1][0] = t4[2]; bh[2 * pr + 1][1] = t4[3];
                ldmatrix_x4(t4, bLO + pr * (16 * 80) + kb + boff);
                bl[2 * pr][0] = t4[0]; bl[2 * pr][1] = t4[1];
                bl[2 * pr + 1][0] = t4[2]; bl[2 * pr + 1][1] = t4[3];
            }
            #pragma unroll
            for (int mt = 0; mt < 4; mt++)
                #pragma unroll
                for (int nt = 0; nt < 8; nt++) {
                    mma16816(acc[mt][nt], ah[mt], bh[nt]);
                    mma16816(acc[mt][nt], ah[mt], bl[nt]);
                    mma16816(acc[mt][nt], al[mt], bh[nt]);
                }
        }
        __syncthreads();
        if (c + NSTG < GNCHUNK) load_chunk(c + NSTG, s);
        CP_COMMIT();
    }

    // ------------------- epilogue -------------------
    const int g4 = lid >> 2, t2 = lid & 3;
    const int h = (n0 + wn * 64) >> 6;           // one head per warp column
    float fe = 0.f, fo = 0.f;
    #pragma unroll
    for (int nt = 0; nt < 8; nt++) {
        int n = n0 + wn * 64 + nt * 8 + t2 * 2;
        float bi0 = bias[n], bi1 = bias[n + 1];
        int d = n & 63;
        if (mode == MODE_ROPEQ || mode == MODE_ROPEK) {
            fe = powf(10000.0f, -(float)(2 * (d & 31)) / 64.0f);
            fo = powf(10000.0f, -(float)(2 * ((d + 1) & 31)) / 64.0f);
        }
        #pragma unroll
        for (int mt = 0; mt < 4; mt++) {
            #pragma unroll
            for (int hf = 0; hf < 2; hf++) {
                int m = m0 + wm * 64 + mt * 16 + g4 + hf * 8;
                float v0 = acc[mt][nt][hf * 2 + 0] + bi0;
                float v1 = acc[mt][nt][hf * 2 + 1] + bi1;
                if (mode == MODE_PLAIN) {
                    float2 o = {v0, v1};
                    *(float2*)&dstf[(size_t)m * Ev + n] = o;
                } else {
                    int b = m >> 11, srow = m & 2047;
                    if (mode != MODE_BHSD) {
                        float pos = (float)srow;
                        float se, ce, so, co;
                        sincos_red(pos * fe, &se, &ce);
                        sincos_red(pos * fo, &so, &co);
                        float r0 = v0 * ce - v1 * se;
                        float r1 = v1 * co + v0 * so;
                        v0 = r0; v1 = r1;
                        if (mode == MODE_ROPEQ) { v0 *= 0.125f; v1 *= 0.125f; }
                    }
                    uint32_t hw, lw;
                    split_pack(v0, v1, hw, lw);
                    size_t off = (((size_t)(b * Hv + h) * Sv + srow) << 6) + d;
                    *(uint32_t*)&dsthi[off] = hw;
                    *(uint32_t*)&dstlo[off] = lw;
                }
            }
        }
    }
}

// fused Q/K/V projection: blockIdx.z selects weight set + epilogue mode
__global__ __launch_bounds__(256, 1)
void gemm_qkv_kernel(const __nv_bfloat16* __restrict__ xhi,
                     const __nv_bfloat16* __restrict__ xlo,
                     const __nv_bfloat16* __restrict__ wqhi, const __nv_bfloat16* __restrict__ wqlo,
                     const __nv_bfloat16* __restrict__ wkhi, const __nv_bfloat16* __restrict__ wklo,
                     const __nv_bfloat16* __restrict__ wvhi, const __nv_bfloat16* __restrict__ wvlo,
                     const float* __restrict__ bq, const float* __restrict__ bk,
                     const float* __restrict__ bv,
                     __nv_bfloat16* __restrict__ qhi, __nv_bfloat16* __restrict__ qlo,
                     __nv_bfloat16* __restrict__ khi, __nv_bfloat16* __restrict__ klo,
                     __nv_bfloat16* __restrict__ vhi, __nv_bfloat16* __restrict__ vlo)
{
    int z = blockIdx.z;
    const __nv_bfloat16* whi = (z == 0) ? wqhi : (z == 1) ? wkhi : wvhi;
    const __nv_bfloat16* wlo = (z == 0) ? wqlo : (z == 1) ? wklo : wvlo;
    const float* bias = (z == 0) ? bq : (z == 1) ? bk : bv;
    __nv_bfloat16* dhi = (z == 0) ? qhi : (z == 1) ? khi : vhi;
    __nv_bfloat16* dlo = (z == 0) ? qlo : (z == 1) ? klo : vlo;
    int mode = (z == 0) ? MODE_ROPEQ : (z == 1) ? MODE_ROPEK : MODE_BHSD;
    gemm_core(xhi, xlo, whi, wlo, bias, nullptr, dhi, dlo, mode);
}

__global__ __launch_bounds__(256, 1)
void gemm_final_kernel(const __nv_bfloat16* __restrict__ ohi,
                       const __nv_bfloat16* __restrict__ olo,
                       const __nv_bfloat16* __restrict__ wohi,
                       const __nv_bfloat16* __restrict__ wolo,
                       const float* __restrict__ bo, float* __restrict__ out)
{
    gemm_core(ohi, olo, wohi, wolo, bo, out, nullptr, nullptr, MODE_PLAIN);
}

// ---------------------------------------------------------------------------
// Flash attention via mma.sync, bf16x3. CTA = 128 queries of one (b,h).
// 8 warps x 16 query rows. K-tiles of 64, double-buffered cp.async.
// Smem rows padded to 144B -> conflict-free ldmatrix.
// ---------------------------------------------------------------------------
#define PITCHB 144
#define QSMB (128 * PITCHB)          // 18432
#define KVTILE (64 * PITCHB)         // 9216
#define KVSTG (4 * KVTILE)           // 36864
#define ATTN_SMEM (2 * QSMB + 2 * KVSTG)   // 110592

__global__ __launch_bounds__(256, 1)
void attn_mma_kernel(const __nv_bfloat16* __restrict__ Qhi,
                     const __nv_bfloat16* __restrict__ Qlo,
                     const __nv_bfloat16* __restrict__ Khi,
                     const __nv_bfloat16* __restrict__ Klo,
                     const __nv_bfloat16* __restrict__ Vhi,
                     const __nv_bfloat16* __restrict__ Vlo,
                     __nv_bfloat16* __restrict__ Ohi,
                     __nv_bfloat16* __restrict__ Olo)
{
    extern __shared__ char dsm[];
    uint32_t base = smem_to_u32(dsm);
    const int tid = threadIdx.x, wid = tid >> 5, lid = tid & 31;
    const int qt = (int)gridDim.x - 1 - (int)blockIdx.x;  // longest first
    const int bh = blockIdx.y;
    const int nkt = 2 * (qt + 1);
    const size_t bhb = (size_t)bh * Sv * 64;

    const uint32_t qhib = base, qlob = base + QSMB;
    const uint32_t stg = base + 2 * QSMB;

    auto load_kv = [&](int kt, int s) {
        uint32_t sb = stg + s * KVSTG;
        const __nv_bfloat16* srcs[4] = {
            Khi + bhb + (size_t)kt * 64 * 64, Klo + bhb + (size_t)kt * 64 * 64,
            Vhi + bhb + (size_t)kt * 64 * 64, Vlo + bhb + (size_t)kt * 64 * 64 };
        #pragma unroll
        for (int it = 0; it < 8; it++) {
            int e = it * 256 + tid;
            int tl = e >> 9, r = (e >> 3) & 63, ch = e & 7;
            CP_ASYNC16(sb + tl * KVTILE + r * PITCHB + ch * 16,
                       srcs[tl] + r * 64 + ch * 8);
        }
    };

    {
        const __nv_bfloat16* gh = Qhi + bhb + (size_t)qt * 128 * 64;
        const __nv_bfloat16* gl = Qlo + bhb + (size_t)qt * 128 * 64;
        #pragma unroll
        for (int it = 0; it < 4; it++) {
            int e = it * 256 + tid;
            int r = e >> 3, ch = e & 7;
            CP_ASYNC16(qhib + r * PITCHB + ch * 16, gh + r * 64 + ch * 8);
            CP_ASYNC16(qlob + r * PITCHB + ch * 16, gl + r * 64 + ch * 8);
        }
        load_kv(0, 0);
        CP_COMMIT();
        load_kv(1, 1);
        CP_COMMIT();
    }
    CP_WAIT1();
    __syncthreads();

    uint32_t qfh[4][4], qfl[4][4];
    {
        uint32_t qfo = (wid * 16 + (lid & 15)) * PITCHB + (lid >> 4) * 16;
        #pragma unroll
        for (int kc = 0; kc < 4; kc++) {
            ldmatrix_x4(qfh[kc], qhib + qfo + kc * 32);
            ldmatrix_x4(qfl[kc], qlob + qfo + kc * 32);
        }
    }

    float m0 = -1e30f, m1 = -1e30f, l0 = 0.f, l1 = 0.f;
    float accO[8][4] = {};

    const uint32_t kfo = ((lid >> 4) * 8 + (lid & 7)) * PITCHB + ((lid >> 3) & 1) * 16;
    const uint32_t vfo = (lid & 15) * PITCHB + (lid >> 4) * 16;
    const int g4 = lid >> 2, t2 = lid & 3;

    for (int kt = 0; kt < nkt; kt++) {
        uint32_t sb = stg + (kt & 1) * KVSTG;

        float S[8][4] = {};
        #pragma unroll
        for (int kc = 0; kc < 4; kc++) {
            #pragma unroll
            for (int n0t = 0; n0t < 4; n0t++) {
                uint32_t ka = sb + (n0t * 16) * PITCHB + kc * 32 + kfo;
                uint32_t kh[4], kl[4];
                ldmatrix_x4(kh, ka);
                ldmatrix_x4(kl, ka + KVTILE);
                mma16816(S[2 * n0t], qfh[kc], kh);
                mma16816(S[2 * n0t], qfh[kc], kl);
                mma16816(S[2 * n0t], qfl[kc], kh);
                mma16816(S[2 * n0t + 1], qfh[kc], kh + 2);
                mma16816(S[2 * n0t + 1], qfh[kc], kl + 2);
                mma16816(S[2 * n0t + 1], qfl[kc], kh + 2);
            }
        }

        if (kt >= 2 * qt) {
            int j0g = kt * 64, q0g = qt * 128 + wid * 16;
            int colb = t2 * 2, rowb = g4;
            #pragma unroll
            for (int nt = 0; nt < 8; nt++) {
                int jb = j0g + nt * 8 + colb;
                if (jb > q0g + rowb)          S[nt][0] = -1e30f;
                if (jb + 1 > q0g + rowb)      S[nt][1] = -1e30f;
                if (jb > q0g + rowb + 8)      S[nt][2] = -1e30f;
                if (jb + 1 > q0g + rowb + 8)  S[nt][3] = -1e30f;
            }
        }

        float mx0 = -1e30f, mx1 = -1e30f;
        #pragma unroll
        for (int nt = 0; nt < 8; nt++) {
            mx0 = fmaxf(mx0, fmaxf(S[nt][0], S[nt][1]));
            mx1 = fmaxf(mx1, fmaxf(S[nt][2], S[nt][3]));
        }
        mx0 = fmaxf(mx0, __shfl_xor_sync(0xffffffffu, mx0, 1));
        mx0 = fmaxf(mx0, __shfl_xor_sync(0xffffffffu, mx0, 2));
        mx1 = fmaxf(mx1, __shfl_xor_sync(0xffffffffu, mx1, 1));
        mx1 = fmaxf(mx1, __shfl_xor_sync(0xffffffffu, mx1, 2));
        float nm0 = fmaxf(m0, mx0), nm1 = fmaxf(m1, mx1);
        float a0 = __expf(m0 - nm0), a1 = __expf(m1 - nm1);
        m0 = nm0; m1 = nm1;

        float rs0 = 0.f, rs1 = 0.f;
        uint32_t phA[8], phB[8], plA[8], plB[8];
        #pragma unroll
        for (int nt = 0; nt < 8; nt++) {
            float p0 = __expf(S[nt][0] - nm0), p1 = __expf(S[nt][1] - nm0);
            float p2 = __expf(S[nt][2] - nm1), p3 = __expf(S[nt][3] - nm1);
            rs0 += p0 + p1; rs1 += p2 + p3;
            split_pack(p0, p1, phA[nt], plA[nt]);
            split_pack(p2, p3, phB[nt], plB[nt]);
        }
        rs0 += __shfl_xor_sync(0xffffffffu, rs0, 1);
        rs0 += __shfl_xor_sync(0xffffffffu, rs0, 2);
        rs1 += __shfl_xor_sync(0xffffffffu, rs1, 1);
        rs1 += __shfl_xor_sync(0xffffffffu, rs1, 2);
        l0 = l0 * a0 + rs0;
        l1 = l1 * a1 + rs1;
        #pragma unroll
        for (int dt = 0; dt < 8; dt++) {
            accO[dt][0] *= a0; accO[dt][1] *= a0;
            accO[dt][2] *= a1; accO[dt][3] *= a1;
        }

        uint32_t vb = sb + 2 * KVTILE;
        #pragma unroll
        for (int kc = 0; kc < 4; kc++) {
            uint32_t aph[4] = {phA[2 * kc], phB[2 * kc], phA[2 * kc + 1], phB[2 * kc + 1]};
            uint32_t apl[4] = {plA[2 * kc], plB[2 * kc], plA[2 * kc + 1], plB[2 * kc + 1]};
            #pragma unroll
            for (int d0t = 0; d0t < 4; d0t++) {
                uint32_t va = vb + (kc * 16) * PITCHB + d0t * 32 + vfo;
                uint32_t vh[4], vl[4];
                ldmatrix_x4t(vh, va);
                ldmatrix_x4t(vl, va + KVTILE);
                mma16816(accO[2 * d0t], aph, vh);
                mma16816(accO[2 * d0t], apl, vh);
                mma16816(accO[2 * d0t], aph, vl);
                mma16816(accO[2 * d0t + 1], aph, vh + 2);
                mma16816(accO[2 * d0t + 1], apl, vh + 2);
                mma16816(accO[2 * d0t + 1], aph, vl + 2);
            }
        }

        __syncthreads();
        if (kt + 2 < nkt) load_kv(kt + 2, kt & 1);
        CP_COMMIT();
        CP_WAIT1();
        __syncthreads();
    }

    float inv0 = 1.0f / l0, inv1 = 1.0f / l1;
    int b = bh >> 4, h = bh & 15;
    int s0 = qt * 128 + wid * 16 + g4, s1 = s0 + 8;
    size_t r0o = ((size_t)(b * Sv + s0)) * Ev + h * 64;
    size_t r1o = ((size_t)(b * Sv + s1)) * Ev + h * 64;
    #pragma unroll
    for (int dt = 0; dt < 8; dt++) {
        int d = dt * 8 + t2 * 2;
        uint32_t hw, lw;
        split_pack(accO[dt][0] * inv0, accO[dt][1] * inv0, hw, lw);
        *(uint32_t*)&Ohi[r0o + d] = hw;
        *(uint32_t*)&Olo[r0o + d] = lw;
        split_pack(accO[dt][2] * inv1, accO[dt][3] * inv1, hw, lw);
        *(uint32_t*)&Ohi[r1o + d] = hw;
        *(uint32_t*)&Olo[r1o + d] = lw;
    }
}

// ---------------------------------------------------------------------------
extern "C" void kernel_launch(void* const* d_in, const int* in_sizes, int n_in,
                              void* d_out, int out_size)
{
    const float* x  = (const float*)d_in[0];
    const float* wq = (const float*)d_in[1];
    const float* bq = (const float*)d_in[2];
    const float* wk = (const float*)d_in[3];
    const float* bk = (const float*)d_in[4];
    const float* wv = (const float*)d_in[5];
    const float* bv = (const float*)d_in[6];
    const float* wo = (const float*)d_in[7];
    const float* bo = (const float*)d_in[8];
    float* out = (float*)d_out;

    cudaFuncSetAttribute(gemm_qkv_kernel,
                         cudaFuncAttributeMaxDynamicSharedMemorySize, GEMM_SMEM);
    cudaFuncSetAttribute(gemm_final_kernel,
                         cudaFuncAttributeMaxDynamicSharedMemorySize, GEMM_SMEM);
    cudaFuncSetAttribute(attn_mma_kernel,
                         cudaFuncAttributeMaxDynamicSharedMemorySize, ATTN_SMEM);

    __nv_bfloat16 *qhi, *qlo, *khi, *klo, *vhi, *vlo;
    __nv_bfloat16 *xhi, *xlo, *ohi, *olo;
    __nv_bfloat16 *wqhi, *wqlo, *wkhi, *wklo, *wvhi, *wvlo, *wohi, *wolo;
    cudaGetSymbolAddress((void**)&qhi, g_Qhi);
    cudaGetSymbolAddress((void**)&qlo, g_Qlo);
    cudaGetSymbolAddress((void**)&khi, g_Khi);
    cudaGetSymbolAddress((void**)&klo, g_Klo);
    cudaGetSymbolAddress((void**)&vhi, g_Vhi);
    cudaGetSymbolAddress((void**)&vlo, g_Vlo);
    cudaGetSymbolAddress((void**)&xhi, g_xhi);
    cudaGetSymbolAddress((void**)&xlo, g_xlo);
    cudaGetSymbolAddress((void**)&ohi, g_ohi);
    cudaGetSymbolAddress((void**)&olo, g_olo);
    cudaGetSymbolAddress((void**)&wqhi, g_wqhi);
    cudaGetSymbolAddress((void**)&wqlo, g_wqlo);
    cudaGetSymbolAddress((void**)&wkhi, g_wkhi);
    cudaGetSymbolAddress((void**)&wklo, g_wklo);
    cudaGetSymbolAddress((void**)&wvhi, g_wvhi);
    cudaGetSymbolAddress((void**)&wvlo, g_wvlo);
    cudaGetSymbolAddress((void**)&wohi, g_wohi);
    cudaGetSymbolAddress((void**)&wolo, g_wolo);

    const int NX = Mtot * Ev;
    const int NW = Ev * Ev;
    split_bf16_kernel<<<NX / 1024, 256>>>(x, xhi, xlo);
    split4_kernel<<<dim3(NW / 1024, 4), 256>>>(
        wq, wk, wv, wo,
        wqhi, wqlo, wkhi, wklo, wvhi, wvlo, wohi, wolo);

    gemm_qkv_kernel<<<dim3(Ev / 256, Mtot / 128, 3), 256, GEMM_SMEM>>>(
        xhi, xlo, wqhi, wqlo, wkhi, wklo, wvhi, wvlo,
        bq, bk, bv, qhi, qlo, khi, klo, vhi, vlo);

    attn_mma_kernel<<<dim3(Sv / 128, Bv * Hv), 256, ATTN_SMEM>>>(
        qhi, qlo, khi, klo, vhi, vlo, ohi, olo);

    gemm_final_kernel<<<dim3(Ev / 256, Mtot / 128), 256, GEMM_SMEM>>>(
        ohi, olo, wohi, wolo, bo, out);
}